// round 2
// baseline (speedup 1.0000x reference)
#include <cuda_runtime.h>
#include <math.h>

// ---------------------------------------------------------------------------
// LSTM cell with layer norm.  B=4096, IN=1024, H=2048, OUT=1024.
// Inputs (metadata order):
//  0 inp[4096,1024]  1 h_0[4096,2048]  2 c_0[4096,2048]
//  3 Wfh 4 bfh  5 Wih 6 bih  7 Wch 8 bch  9 Woh 10 boh     (H->H,  [2048,2048])
// 11 Wfx 12 bfx 13 Wix 14 bix 15 Wcx 16 bcx 17 Wox 18 box  (IN->H, [2048,1024])
// 19 Wdec[1024,2048] 20 bdec[1024]
// 21 ax 22 bx 23 ah 24 bh 25 ac 26 bc   (each [2048])
// Output: concat(out[4096,1024], hx[4096,2048], cx[4096,2048])
// ---------------------------------------------------------------------------

#define BDIM 4096
#define HDIM 2048
#define EPS_LN 1e-5f

// scratch: X-side gate preacts [4096,8192] and H-side [4096,8192]
__device__ float g_Xbuf[(size_t)BDIM * 4 * HDIM];
__device__ float g_Hbuf[(size_t)BDIM * 4 * HDIM];

// ---------------------------------------------------------------------------
// SGEMM:  C[M, Ntot] = A[M,K] @ W^T + bias, where the Ntot columns are split
// into gates of Npg columns each, gate g using (Wg, Bg).  W is [Npg, K]
// row-major (K contiguous) -> NT GEMM, both operands K-contiguous.
// Tile 128x128x8, 256 threads, 8x8 per thread (split-tile layout).
// ---------------------------------------------------------------------------
__global__ __launch_bounds__(256, 2) void gemm4_kernel(
    const float* __restrict__ A,
    const float* __restrict__ W0, const float* __restrict__ W1,
    const float* __restrict__ W2, const float* __restrict__ W3,
    const float* __restrict__ B0, const float* __restrict__ B1,
    const float* __restrict__ B2, const float* __restrict__ B3,
    float* __restrict__ C, int K, int Npg, int Ntot)
{
    __shared__ float As[8][128];
    __shared__ float Ws[8][128];

    const int tid = threadIdx.x;
    const int bm  = blockIdx.x;
    const int bn  = blockIdx.y;

    const int gate  = (bn * 128) / Npg;          // whole block lies in one gate
    const int wbase = bn * 128 - gate * Npg;     // column offset within gate

    const float* W  = (gate == 0) ? W0 : (gate == 1) ? W1 : (gate == 2) ? W2 : W3;
    const float* Bv = (gate == 0) ? B0 : (gate == 1) ? B1 : (gate == 2) ? B2 : B3;

    const int lrow = tid >> 1;          // 0..127
    const int lcol = (tid & 1) * 4;     // 0 or 4
    const float* Aptr = A + (size_t)(bm * 128 + lrow) * K + lcol;
    const float* Wptr = W + (size_t)(wbase + lrow) * K + lcol;

    const int tx = tid & 15;            // 0..15
    const int ty = tid >> 4;            // 0..15

    float acc[8][8];
    #pragma unroll
    for (int i = 0; i < 8; i++)
        #pragma unroll
        for (int j = 0; j < 8; j++) acc[i][j] = 0.0f;

    for (int k0 = 0; k0 < K; k0 += 8) {
        const float4 av = *(const float4*)(Aptr + k0);
        const float4 wv = *(const float4*)(Wptr + k0);
        __syncthreads();
        As[lcol + 0][lrow] = av.x; As[lcol + 1][lrow] = av.y;
        As[lcol + 2][lrow] = av.z; As[lcol + 3][lrow] = av.w;
        Ws[lcol + 0][lrow] = wv.x; Ws[lcol + 1][lrow] = wv.y;
        Ws[lcol + 2][lrow] = wv.z; Ws[lcol + 3][lrow] = wv.w;
        __syncthreads();
        #pragma unroll
        for (int k = 0; k < 8; ++k) {
            float a[8], b[8];
            *(float4*)&a[0] = *(const float4*)&As[k][ty * 4];
            *(float4*)&a[4] = *(const float4*)&As[k][64 + ty * 4];
            *(float4*)&b[0] = *(const float4*)&Ws[k][tx * 4];
            *(float4*)&b[4] = *(const float4*)&Ws[k][64 + tx * 4];
            #pragma unroll
            for (int i = 0; i < 8; i++)
                #pragma unroll
                for (int j = 0; j < 8; j++)
                    acc[i][j] = fmaf(a[i], b[j], acc[i][j]);
        }
    }

    // epilogue: add bias, store (two float4 per row fragment)
    #pragma unroll
    for (int i = 0; i < 8; i++) {
        const int r = bm * 128 + ((i < 4) ? (ty * 4 + i) : (64 + ty * 4 + (i - 4)));
        #pragma unroll
        for (int jj = 0; jj < 2; jj++) {
            const int cbase = (jj == 0) ? (tx * 4) : (64 + tx * 4);
            float4 v;
            v.x = acc[i][jj * 4 + 0] + Bv[wbase + cbase + 0];
            v.y = acc[i][jj * 4 + 1] + Bv[wbase + cbase + 1];
            v.z = acc[i][jj * 4 + 2] + Bv[wbase + cbase + 2];
            v.w = acc[i][jj * 4 + 3] + Bv[wbase + cbase + 3];
            *(float4*)&C[(size_t)r * Ntot + bn * 128 + cbase] = v;
        }
    }
}

// ---------------------------------------------------------------------------
// Per-(row, gate) layer norm of the x-side and h-side preactivations, summed:
//   G = LN(X; ax, bx) + LN(H; ah, bh)
// LN uses unbiased std (ddof=1) and eps added to sigma (torch module match).
// Writes G back into Xbuf in place.  blockIdx = (row, gate), 256 threads x 8.
// ---------------------------------------------------------------------------
__global__ __launch_bounds__(256) void ln_combine_kernel(
    float* __restrict__ Xbuf, const float* __restrict__ Hbuf,
    const float* __restrict__ ax, const float* __restrict__ bxv,
    const float* __restrict__ ah, const float* __restrict__ bhv)
{
    const int row  = blockIdx.x;
    const int gate = blockIdx.y;
    const size_t base = (size_t)row * (4 * HDIM) + (size_t)gate * HDIM;
    const int tid = threadIdx.x;

    float x[8], h[8];
    float sx = 0.f, sxx = 0.f, sh = 0.f, shh = 0.f;
    #pragma unroll
    for (int i = 0; i < 8; i++) {
        const int c = tid + i * 256;
        x[i] = Xbuf[base + c];
        h[i] = Hbuf[base + c];
        sx += x[i]; sxx += x[i] * x[i];
        sh += h[i]; shh += h[i] * h[i];
    }

    __shared__ float4 red[256];
    red[tid] = make_float4(sx, sxx, sh, shh);
    __syncthreads();
    #pragma unroll
    for (int s = 128; s > 0; s >>= 1) {
        if (tid < s) {
            float4 o = red[tid + s], m = red[tid];
            red[tid] = make_float4(m.x + o.x, m.y + o.y, m.z + o.z, m.w + o.w);
        }
        __syncthreads();
    }
    const float4 t = red[0];
    const float n = (float)HDIM;
    const float mux = t.x / n, muh = t.z / n;
    const float vx = (t.y - n * mux * mux) / (n - 1.0f);
    const float vh = (t.w - n * muh * muh) / (n - 1.0f);
    const float rx = 1.0f / (sqrtf(fmaxf(vx, 0.f)) + EPS_LN);
    const float rh = 1.0f / (sqrtf(fmaxf(vh, 0.f)) + EPS_LN);

    #pragma unroll
    for (int i = 0; i < 8; i++) {
        const int c = tid + i * 256;
        const float g = (x[i] - mux) * rx * ax[c] + bxv[c]
                      + (h[i] - muh) * rh * ah[c] + bhv[c];
        Xbuf[base + c] = g;
    }
}

// ---------------------------------------------------------------------------
// Cell body: gates -> cx, per-row LN of cx, hx.  blockIdx = row.
//   f,i,o = sigmoid(G), ct = tanh(Gc), cx = f*c0 + i*ct
//   hx = o * tanh(LN(cx; ac, bc))
// ---------------------------------------------------------------------------
__global__ __launch_bounds__(256) void cell_kernel(
    const float* __restrict__ G, const float* __restrict__ c0,
    const float* __restrict__ ac, const float* __restrict__ bcv,
    float* __restrict__ hx_out, float* __restrict__ cx_out)
{
    const int row = blockIdx.x;
    const int tid = threadIdx.x;
    const size_t base = (size_t)row * (4 * HDIM);

    float cv[8], og[8];
    float s = 0.f, ss = 0.f;
    #pragma unroll
    for (int i = 0; i < 8; i++) {
        const int c = tid + i * 256;
        const float gf = G[base + c];
        const float gi = G[base + HDIM + c];
        const float gc = G[base + 2 * HDIM + c];
        const float go = G[base + 3 * HDIM + c];
        const float fg = 1.0f / (1.0f + expf(-gf));
        const float ig = 1.0f / (1.0f + expf(-gi));
        const float ct = tanhf(gc);
        const float v = fg * c0[(size_t)row * HDIM + c] + ig * ct;
        cv[i] = v; og[i] = go;
        s += v; ss += v * v;
    }

    __shared__ float2 red[256];
    red[tid] = make_float2(s, ss);
    __syncthreads();
    #pragma unroll
    for (int st = 128; st > 0; st >>= 1) {
        if (tid < st) {
            float2 o = red[tid + st], m = red[tid];
            red[tid] = make_float2(m.x + o.x, m.y + o.y);
        }
        __syncthreads();
    }
    const float2 t = red[0];
    const float n = (float)HDIM;
    const float mu = t.x / n;
    const float var = (t.y - n * mu * mu) / (n - 1.0f);
    const float rs = 1.0f / (sqrtf(fmaxf(var, 0.f)) + EPS_LN);

    #pragma unroll
    for (int i = 0; i < 8; i++) {
        const int c = tid + i * 256;
        const float lnc = (cv[i] - mu) * rs * ac[c] + bcv[c];
        const float o = 1.0f / (1.0f + expf(-og[i]));
        hx_out[(size_t)row * HDIM + c] = o * tanhf(lnc);
        cx_out[(size_t)row * HDIM + c] = cv[i];
    }
}

// ---------------------------------------------------------------------------
extern "C" void kernel_launch(void* const* d_in, const int* in_sizes, int n_in,
                              void* d_out, int out_size)
{
    (void)in_sizes; (void)n_in; (void)out_size;
    const float* inp = (const float*)d_in[0];
    const float* h0  = (const float*)d_in[1];
    const float* c0  = (const float*)d_in[2];
    const float* Wfh = (const float*)d_in[3];   const float* bfh = (const float*)d_in[4];
    const float* Wih = (const float*)d_in[5];   const float* bih = (const float*)d_in[6];
    const float* Wch = (const float*)d_in[7];   const float* bch = (const float*)d_in[8];
    const float* Woh = (const float*)d_in[9];   const float* boh = (const float*)d_in[10];
    const float* Wfx = (const float*)d_in[11];  const float* bfx = (const float*)d_in[12];
    const float* Wix = (const float*)d_in[13];  const float* bix = (const float*)d_in[14];
    const float* Wcx = (const float*)d_in[15];  const float* bcx = (const float*)d_in[16];
    const float* Wox = (const float*)d_in[17];  const float* box_ = (const float*)d_in[18];
    const float* Wdec = (const float*)d_in[19]; const float* bdec = (const float*)d_in[20];
    const float* ax = (const float*)d_in[21];   const float* bx = (const float*)d_in[22];
    const float* ah = (const float*)d_in[23];   const float* bh = (const float*)d_in[24];
    const float* ac = (const float*)d_in[25];   const float* bc = (const float*)d_in[26];

    float* Xbuf = nullptr;
    float* Hbuf = nullptr;
    cudaGetSymbolAddress((void**)&Xbuf, g_Xbuf);
    cudaGetSymbolAddress((void**)&Hbuf, g_Hbuf);

    float* out = (float*)d_out;
    float* hx  = out + (size_t)BDIM * 1024;
    float* cx  = hx + (size_t)BDIM * HDIM;

    const dim3 blk(256);

    // x-side gate preactivations: [4096, 8192] = inp @ [Wfx;Wix;Wcx;Wox]^T + b
    gemm4_kernel<<<dim3(BDIM / 128, (4 * HDIM) / 128), blk>>>(
        inp, Wfx, Wix, Wcx, Wox, bfx, bix, bcx, box_,
        Xbuf, 1024, HDIM, 4 * HDIM);

    // h-side gate preactivations: [4096, 8192] = h0 @ [Wfh;Wih;Wch;Woh]^T + b
    gemm4_kernel<<<dim3(BDIM / 128, (4 * HDIM) / 128), blk>>>(
        h0, Wfh, Wih, Wch, Woh, bfh, bih, bch, boh,
        Hbuf, HDIM, HDIM, 4 * HDIM);

    // G = LN(X) + LN(H), in place into Xbuf
    ln_combine_kernel<<<dim3(BDIM, 4), blk>>>(Xbuf, Hbuf, ax, bx, ah, bh);

    // cell: cx, hx (written directly into output regions)
    cell_kernel<<<dim3(BDIM), blk>>>(Xbuf, c0, ac, bc, hx, cx);

    // decoder: out = hx @ Wdec^T + bdec
    gemm4_kernel<<<dim3(BDIM / 128, 1024 / 128), blk>>>(
        hx, Wdec, Wdec, Wdec, Wdec, bdec, bdec, bdec, bdec,
        out, HDIM, 1024, 1024);
}

// round 5
// speedup vs baseline: 2.1470x; 2.1470x over previous
#include <cuda_runtime.h>
#include <cuda_bf16.h>
#include <stdint.h>
#include <math.h>

// ---------------------------------------------------------------------------
// LN-LSTM cell.  B=4096, IN=1024, H=2048, OUT=1024.
// GEMMs via mma.sync bf16 (HMMA) with hi/lo split: A_cat=[hi|lo|hi],
// W_cat=[hi|hi|lo] along K (3K), fp32 accumulation.
// (tcgen05 is unavailable: harness compiles at virtual target sm_103, no 'a'.)
// ---------------------------------------------------------------------------

#define BDIM 4096
#define HDIM 2048
#define EPS_LN 1e-5f

// fp32 scratch for gate preactivations
__device__ float g_Xbuf[(size_t)BDIM * 4 * HDIM];
__device__ float g_Hbuf[(size_t)BDIM * 4 * HDIM];
// bf16 split-cat operands
__device__ __nv_bfloat16 g_Ax[(size_t)BDIM * 3 * 1024];
__device__ __nv_bfloat16 g_Ah[(size_t)BDIM * 3 * HDIM];
__device__ __nv_bfloat16 g_Wx[(size_t)4 * HDIM * 3 * 1024];
__device__ __nv_bfloat16 g_Wh[(size_t)4 * HDIM * 3 * HDIM];
__device__ __nv_bfloat16 g_Wd[(size_t)1024 * 3 * HDIM];
__device__ __nv_bfloat16 g_Hxc[(size_t)BDIM * 3 * HDIM];
__device__ float g_biasx[4 * HDIM];
__device__ float g_biash[4 * HDIM];

// ------------------------------- helpers -----------------------------------
__device__ __forceinline__ uint32_t smem_u32(const void* p) {
    uint32_t a;
    asm("{ .reg .u64 t; cvta.to.shared.u64 t, %1; cvt.u32.u64 %0, t; }" : "=r"(a) : "l"(p));
    return a;
}
#define CP_ASYNC16(dst, src) \
    asm volatile("cp.async.cg.shared.global [%0], [%1], 16;" :: "r"(dst), "l"(src) : "memory")
#define CP_COMMIT()  asm volatile("cp.async.commit_group;" ::: "memory")
#define CP_WAIT1()   asm volatile("cp.async.wait_group 1;" ::: "memory")

// ---------------------------------------------------------------------------
// HMMA GEMM:  C[4096, Ntot] = Acat[M,Kcat] * Wcat[Ntot,Kcat]^T + bias
// CTA 128x128, BK=64, 3-stage cp.async, 8 warps of 64x32, m16n8k16 bf16.
// ---------------------------------------------------------------------------
#define BM 128
#define BN 128
#define BK 64
#define NSTG 3
#define STG_BYTES 32768                 // A(16KB) + B(16KB)
#define GEMM_SMEM (NSTG * STG_BYTES)    // 98304

__global__ void __launch_bounds__(256, 2) gemm_mma(
    const __nv_bfloat16* __restrict__ A, const __nv_bfloat16* __restrict__ W,
    const float* __restrict__ bias, float* __restrict__ C, int Kcat, int Ntot)
{
    extern __shared__ char smem[];
    const uint32_t sb = smem_u32(smem);
    const int tid  = threadIdx.x;
    const int lane = tid & 31, wid = tid >> 5;
    const int wm = wid & 1, wn = wid >> 1;            // warp grid 2 x 4
    const int m0 = blockIdx.x * BM, n0 = blockIdx.y * BN;
    const int nkt = Kcat / BK;

    // cp.async: thread -> (row, half-row); each thread copies 4x16B per tile side
    const int lrow  = tid >> 1;
    const int lhalf = tid & 1;
    const __nv_bfloat16* agp = A + (size_t)(m0 + lrow) * Kcat + lhalf * 32;
    const __nv_bfloat16* bgp = W + (size_t)(n0 + lrow) * Kcat + lhalf * 32;

#define LOADT(kt, stg) do {                                                     \
    const __nv_bfloat16* a_ = agp + (size_t)(kt) * BK;                          \
    const __nv_bfloat16* b_ = bgp + (size_t)(kt) * BK;                          \
    const uint32_t as_ = sb + (stg) * STG_BYTES;                                \
    const uint32_t bs_ = as_ + 16384;                                           \
    _Pragma("unroll")                                                           \
    for (int j = 0; j < 4; j++) {                                               \
        const uint32_t g   = lhalf * 4 + j;                                     \
        const uint32_t off = lrow * 128 + ((g ^ (lrow & 7)) << 4);              \
        CP_ASYNC16(as_ + off, a_ + j * 8);                                      \
        CP_ASYNC16(bs_ + off, b_ + j * 8);                                      \
    }                                                                           \
} while (0)

    // ldmatrix addressing
    const int a_r16 = lane & 15;          // row within 16
    const int a_h   = lane >> 4;          // k16 half (0=lo16B,1=hi16B)
    const int b_sel = lane >> 3, b_tr = lane & 7;
    const int b_roff = ((b_sel >> 1) & 1) * 8 + b_tr;  // row within 16
    const int b_h    = b_sel & 1;

    float acc[4][4][4];
    #pragma unroll
    for (int i = 0; i < 4; i++)
        #pragma unroll
        for (int j = 0; j < 4; j++)
            #pragma unroll
            for (int q = 0; q < 4; q++) acc[i][j][q] = 0.0f;

    LOADT(0, 0); CP_COMMIT();
    LOADT(1, 1); CP_COMMIT();

    for (int kt = 0; kt < nkt; kt++) {
        const int stg = kt % NSTG;
        CP_WAIT1();
        __syncthreads();
        const uint32_t as_ = sb + stg * STG_BYTES;
        const uint32_t bs_ = as_ + 16384;

        #pragma unroll
        for (int kk = 0; kk < 4; kk++) {
            uint32_t a[4][4], b[2][4];
            #pragma unroll
            for (int mf = 0; mf < 4; mf++) {
                const int r = wm * 64 + mf * 16 + a_r16;
                const uint32_t ad = as_ + r * 128 + (((kk * 2 + a_h) ^ (r & 7)) << 4);
                asm volatile("ldmatrix.sync.aligned.m8n8.x4.shared.b16 {%0,%1,%2,%3}, [%4];"
                    : "=r"(a[mf][0]), "=r"(a[mf][1]), "=r"(a[mf][2]), "=r"(a[mf][3])
                    : "r"(ad));
            }
            #pragma unroll
            for (int p = 0; p < 2; p++) {
                const int r = wn * 32 + p * 16 + b_roff;
                const uint32_t bd = bs_ + r * 128 + (((kk * 2 + b_h) ^ (r & 7)) << 4);
                asm volatile("ldmatrix.sync.aligned.m8n8.x4.shared.b16 {%0,%1,%2,%3}, [%4];"
                    : "=r"(b[p][0]), "=r"(b[p][1]), "=r"(b[p][2]), "=r"(b[p][3])
                    : "r"(bd));
            }
            #pragma unroll
            for (int mf = 0; mf < 4; mf++)
                #pragma unroll
                for (int nf = 0; nf < 4; nf++) {
                    const uint32_t b0 = b[nf >> 1][(nf & 1) * 2 + 0];
                    const uint32_t b1 = b[nf >> 1][(nf & 1) * 2 + 1];
                    asm volatile(
                        "mma.sync.aligned.m16n8k16.row.col.f32.bf16.bf16.f32 "
                        "{%0,%1,%2,%3}, {%4,%5,%6,%7}, {%8,%9}, {%0,%1,%2,%3};"
                        : "+f"(acc[mf][nf][0]), "+f"(acc[mf][nf][1]),
                          "+f"(acc[mf][nf][2]), "+f"(acc[mf][nf][3])
                        : "r"(a[mf][0]), "r"(a[mf][1]), "r"(a[mf][2]), "r"(a[mf][3]),
                          "r"(b0), "r"(b1));
                }
        }
        if (kt + NSTG - 1 < nkt) LOADT(kt + NSTG - 1, (kt + NSTG - 1) % NSTG);
        CP_COMMIT();
    }

    // epilogue: bias + store
    const int er = lane >> 2, ec = (lane & 3) * 2;
    #pragma unroll
    for (int mf = 0; mf < 4; mf++) {
        const int grow = m0 + wm * 64 + mf * 16 + er;
        #pragma unroll
        for (int nf = 0; nf < 4; nf++) {
            const int gcol = n0 + wn * 32 + nf * 8 + ec;
            const float bx0 = __ldg(bias + gcol), bx1 = __ldg(bias + gcol + 1);
            float2 v0 = make_float2(acc[mf][nf][0] + bx0, acc[mf][nf][1] + bx1);
            float2 v1 = make_float2(acc[mf][nf][2] + bx0, acc[mf][nf][3] + bx1);
            *(float2*)&C[(size_t)grow * Ntot + gcol] = v0;
            *(float2*)&C[(size_t)(grow + 8) * Ntot + gcol] = v1;
        }
    }
}

// ---------------------------------------------------------------------------
// split fp32 -> bf16 hi/lo cat.  mode 0 (activations): [hi | lo | hi]
//                                mode 1 (weights):     [hi | hi | lo]
// ---------------------------------------------------------------------------
__global__ void __launch_bounds__(256) split_kernel(
    const float* __restrict__ in, __nv_bfloat16* __restrict__ out, int K, int mode)
{
    const int row = blockIdx.x;
    const float* src = in + (size_t)row * K;
    __nv_bfloat16* d = out + (size_t)row * 3 * K;
    for (int c = threadIdx.x; c < K; c += 256) {
        const float x = src[c];
        const __nv_bfloat16 hi = __float2bfloat16(x);
        const __nv_bfloat16 lo = __float2bfloat16(x - __bfloat162float(hi));
        if (mode == 0) { d[c] = hi; d[K + c] = lo; d[2 * K + c] = hi; }
        else           { d[c] = hi; d[K + c] = hi; d[2 * K + c] = lo; }
    }
}

__global__ void __launch_bounds__(256) bias4_kernel(
    const float* __restrict__ b0, const float* __restrict__ b1,
    const float* __restrict__ b2, const float* __restrict__ b3, float* __restrict__ out)
{
    const int i = blockIdx.x * 256 + threadIdx.x;
    const int g = i >> 11, c = i & 2047;
    out[i] = (g == 0) ? b0[c] : (g == 1) ? b1[c] : (g == 2) ? b2[c] : b3[c];
}

// ---------------------------------------------------------------------------
// LN combine: G = LN(X;ax,bx) + LN(H;ah,bh), in place into Xbuf.
// ---------------------------------------------------------------------------
__global__ void __launch_bounds__(256) ln_combine_kernel(
    float* __restrict__ Xbuf, const float* __restrict__ Hbuf,
    const float* __restrict__ ax, const float* __restrict__ bxv,
    const float* __restrict__ ah, const float* __restrict__ bhv)
{
    const int row = blockIdx.x, gate = blockIdx.y, tid = threadIdx.x;
    const size_t base = (size_t)row * (4 * HDIM) + (size_t)gate * HDIM;

    float x[8], h[8];
    float sx = 0.f, sxx = 0.f, sh = 0.f, shh = 0.f;
    #pragma unroll
    for (int i = 0; i < 8; i++) {
        const int c = tid + i * 256;
        x[i] = Xbuf[base + c]; h[i] = Hbuf[base + c];
        sx += x[i]; sxx += x[i] * x[i];
        sh += h[i]; shh += h[i] * h[i];
    }
    __shared__ float4 red[256];
    red[tid] = make_float4(sx, sxx, sh, shh);
    __syncthreads();
    #pragma unroll
    for (int s = 128; s > 0; s >>= 1) {
        if (tid < s) {
            float4 o = red[tid + s], m = red[tid];
            red[tid] = make_float4(m.x + o.x, m.y + o.y, m.z + o.z, m.w + o.w);
        }
        __syncthreads();
    }
    const float4 t = red[0];
    const float n = (float)HDIM;
    const float mux = t.x / n, muh = t.z / n;
    const float vx = (t.y - n * mux * mux) / (n - 1.0f);
    const float vh = (t.w - n * muh * muh) / (n - 1.0f);
    const float rx = 1.0f / (sqrtf(fmaxf(vx, 0.f)) + EPS_LN);
    const float rh = 1.0f / (sqrtf(fmaxf(vh, 0.f)) + EPS_LN);
    #pragma unroll
    for (int i = 0; i < 8; i++) {
        const int c = tid + i * 256;
        Xbuf[base + c] = (x[i] - mux) * rx * ax[c] + bxv[c]
                       + (h[i] - muh) * rh * ah[c] + bhv[c];
    }
}

// ---------------------------------------------------------------------------
// Cell: gates -> cx, row-LN(cx), hx; also emits hx split-cat bf16 for decoder.
// ---------------------------------------------------------------------------
__global__ void __launch_bounds__(256) cell_kernel(
    const float* __restrict__ G, const float* __restrict__ c0,
    const float* __restrict__ ac, const float* __restrict__ bcv,
    float* __restrict__ hx_out, float* __restrict__ cx_out,
    __nv_bfloat16* __restrict__ hxcat)
{
    const int row = blockIdx.x, tid = threadIdx.x;
    const size_t base = (size_t)row * (4 * HDIM);

    float cv[8], og[8];
    float s = 0.f, ss = 0.f;
    #pragma unroll
    for (int i = 0; i < 8; i++) {
        const int c = tid + i * 256;
        const float gf = G[base + c];
        const float gi = G[base + HDIM + c];
        const float gc = G[base + 2 * HDIM + c];
        const float go = G[base + 3 * HDIM + c];
        const float fg = 1.0f / (1.0f + expf(-gf));
        const float ig = 1.0f / (1.0f + expf(-gi));
        const float v = fg * c0[(size_t)row * HDIM + c] + ig * tanhf(gc);
        cv[i] = v; og[i] = go;
        s += v; ss += v * v;
    }
    __shared__ float2 red[256];
    red[tid] = make_float2(s, ss);
    __syncthreads();
    #pragma unroll
    for (int st = 128; st > 0; st >>= 1) {
        if (tid < st) {
            float2 o = red[tid + st], m = red[tid];
            red[tid] = make_float2(m.x + o.x, m.y + o.y);
        }
        __syncthreads();
    }
    const float2 t = red[0];
    const float n = (float)HDIM;
    const float mu = t.x / n;
    const float var = (t.y - n * mu * mu) / (n - 1.0f);
    const float rs = 1.0f / (sqrtf(fmaxf(var, 0.f)) + EPS_LN);

    __nv_bfloat16* hrow = hxcat + (size_t)row * (3 * HDIM);
    #pragma unroll
    for (int i = 0; i < 8; i++) {
        const int c = tid + i * 256;
        const float lnc = (cv[i] - mu) * rs * ac[c] + bcv[c];
        const float o = 1.0f / (1.0f + expf(-og[i]));
        const float hv = o * tanhf(lnc);
        hx_out[(size_t)row * HDIM + c] = hv;
        cx_out[(size_t)row * HDIM + c] = cv[i];
        const __nv_bfloat16 hi = __float2bfloat16(hv);
        const __nv_bfloat16 lo = __float2bfloat16(hv - __bfloat162float(hi));
        hrow[c] = hi; hrow[HDIM + c] = lo; hrow[2 * HDIM + c] = hi;
    }
}

// ---------------------------------------------------------------------------
extern "C" void kernel_launch(void* const* d_in, const int* in_sizes, int n_in,
                              void* d_out, int out_size)
{
    (void)in_sizes; (void)n_in; (void)out_size;
    const float* inp = (const float*)d_in[0];
    const float* h0  = (const float*)d_in[1];
    const float* c0  = (const float*)d_in[2];
    const float* Wfh = (const float*)d_in[3];   const float* bfh = (const float*)d_in[4];
    const float* Wih = (const float*)d_in[5];   const float* bih = (const float*)d_in[6];
    const float* Wch = (const float*)d_in[7];   const float* bch = (const float*)d_in[8];
    const float* Woh = (const float*)d_in[9];   const float* boh = (const float*)d_in[10];
    const float* Wfx = (const float*)d_in[11];  const float* bfx = (const float*)d_in[12];
    const float* Wix = (const float*)d_in[13];  const float* bix = (const float*)d_in[14];
    const float* Wcx = (const float*)d_in[15];  const float* bcx = (const float*)d_in[16];
    const float* Wox = (const float*)d_in[17];  const float* box_ = (const float*)d_in[18];
    const float* Wdec = (const float*)d_in[19]; const float* bdec = (const float*)d_in[20];
    const float* ax = (const float*)d_in[21];   const float* bx = (const float*)d_in[22];
    const float* ah = (const float*)d_in[23];   const float* bh = (const float*)d_in[24];
    const float* ac = (const float*)d_in[25];   const float* bc = (const float*)d_in[26];

    float *Xbuf, *Hbuf, *biasx, *biash;
    __nv_bfloat16 *Ax, *Ah, *Wx, *Wh, *Wd, *Hxc;
    cudaGetSymbolAddress((void**)&Xbuf, g_Xbuf);
    cudaGetSymbolAddress((void**)&Hbuf, g_Hbuf);
    cudaGetSymbolAddress((void**)&Ax, g_Ax);
    cudaGetSymbolAddress((void**)&Ah, g_Ah);
    cudaGetSymbolAddress((void**)&Wx, g_Wx);
    cudaGetSymbolAddress((void**)&Wh, g_Wh);
    cudaGetSymbolAddress((void**)&Wd, g_Wd);
    cudaGetSymbolAddress((void**)&Hxc, g_Hxc);
    cudaGetSymbolAddress((void**)&biasx, g_biasx);
    cudaGetSymbolAddress((void**)&biash, g_biash);

    cudaFuncSetAttribute(gemm_mma, cudaFuncAttributeMaxDynamicSharedMemorySize, GEMM_SMEM);

    float* out = (float*)d_out;
    float* hx  = out + (size_t)BDIM * 1024;
    float* cx  = hx + (size_t)BDIM * HDIM;

    // split-cat conversions
    split_kernel<<<BDIM, 256>>>(inp, Ax, 1024, 0);
    split_kernel<<<BDIM, 256>>>(h0,  Ah, HDIM, 0);
    split_kernel<<<HDIM, 256>>>(Wfx, Wx + (size_t)0 * HDIM * 3072, 1024, 1);
    split_kernel<<<HDIM, 256>>>(Wix, Wx + (size_t)1 * HDIM * 3072, 1024, 1);
    split_kernel<<<HDIM, 256>>>(Wcx, Wx + (size_t)2 * HDIM * 3072, 1024, 1);
    split_kernel<<<HDIM, 256>>>(Wox, Wx + (size_t)3 * HDIM * 3072, 1024, 1);
    split_kernel<<<HDIM, 256>>>(Wfh, Wh + (size_t)0 * HDIM * 6144, HDIM, 1);
    split_kernel<<<HDIM, 256>>>(Wih, Wh + (size_t)1 * HDIM * 6144, HDIM, 1);
    split_kernel<<<HDIM, 256>>>(Wch, Wh + (size_t)2 * HDIM * 6144, HDIM, 1);
    split_kernel<<<HDIM, 256>>>(Woh, Wh + (size_t)3 * HDIM * 6144, HDIM, 1);
    split_kernel<<<1024, 256>>>(Wdec, Wd, HDIM, 1);
    bias4_kernel<<<32, 256>>>(bfx, bix, bcx, box_, biasx);
    bias4_kernel<<<32, 256>>>(bfh, bih, bch, boh, biash);

    // GEMMs on tensor cores (HMMA)
    gemm_mma<<<dim3(BDIM / BM, (4 * HDIM) / BN), 256, GEMM_SMEM>>>(
        Ax, Wx, biasx, Xbuf, 3 * 1024, 4 * HDIM);
    gemm_mma<<<dim3(BDIM / BM, (4 * HDIM) / BN), 256, GEMM_SMEM>>>(
        Ah, Wh, biash, Hbuf, 3 * HDIM, 4 * HDIM);

    ln_combine_kernel<<<dim3(BDIM, 4), 256>>>(Xbuf, Hbuf, ax, bx, ah, bh);
    cell_kernel<<<BDIM, 256>>>(Xbuf, c0, ac, bc, hx, cx, Hxc);

    gemm_mma<<<dim3(BDIM / BM, 1024 / BN), 256, GEMM_SMEM>>>(
        Hxc, Wd, bdec, out, 3 * HDIM, 1024);
}